// round 1
// baseline (speedup 1.0000x reference)
#include <cuda_runtime.h>
#include <math.h>
#include <float.h>

#define B_    4
#define N_    8192
#define IND   1024
#define HID   512
#define HEADS 8
#define TOPK  16
#define NCLS  2
#define HH    91
#define NPAD  8281   /* HH*HH */
#define NTOK  8282   /* NPAD + 1 cls */
#define DH    64     /* HID/HEADS */

// ---------------- scratch (no allocations allowed) ----------------
__device__ __align__(128) float g_x[B_ * N_ * HID];        // feat GEMM out (pre/post relu)
__device__ __align__(128) float g_scores[B_ * N_];          // pre-sigmoid gate logits
__device__ __align__(128) int   g_topk[B_ * TOPK];
__device__ __align__(128) float g_Q[B_ * HID];
__device__ __align__(128) float g_x3[B_ * NTOK * HID];      // cls + conv-residual tokens
__device__ __align__(128) float g_kk[B_ * NTOK * HID];
__device__ __align__(128) float g_v [B_ * NTOK * HID];
__device__ __align__(128) float g_q [B_ * HID];
__device__ __align__(128) float g_logits[B_ * HEADS * NTOK];
__device__ __align__(128) float g_stats[B_ * HEADS * 2];
__device__ __align__(128) float g_O [B_ * HID];

// ---------------- tiled fp32 GEMM: C = A(MxK) @ B(KxN) + bias ----------------
// BM=BN=64, BK=16, 256 threads, 4x4 register tile per thread.
__global__ void __launch_bounds__(256) sgemm_bias(
    const float* __restrict__ A, const float* __restrict__ Bm,
    const float* __restrict__ bias, float* __restrict__ C,
    int M, int N, int K)
{
    __shared__ __align__(16) float As[16][68];
    __shared__ __align__(16) float Bs[16][64];
    const int tid  = threadIdx.x;
    const int brow = blockIdx.y * 64;
    const int bcol = blockIdx.x * 64;
    const int tr = (tid >> 4) * 4;   // 0..60
    const int tc = (tid & 15) * 4;   // 0..60
    const int a_r = tid >> 2;        // 0..63
    const int a_c = (tid & 3) << 2;  // 0,4,8,12
    const int b_r = tid >> 4;        // 0..15
    const int b_c = (tid & 15) << 2; // 0..60

    float acc[4][4] = {};
    const bool arow_ok = (brow + a_r) < M;
    const float* Ap = A + (size_t)(brow + a_r) * K + a_c;

    for (int k0 = 0; k0 < K; k0 += 16) {
        float4 av = make_float4(0.f, 0.f, 0.f, 0.f);
        if (arow_ok) av = *(const float4*)(Ap + k0);
        As[a_c + 0][a_r] = av.x;
        As[a_c + 1][a_r] = av.y;
        As[a_c + 2][a_r] = av.z;
        As[a_c + 3][a_r] = av.w;
        *(float4*)&Bs[b_r][b_c] =
            *(const float4*)(Bm + (size_t)(k0 + b_r) * N + bcol + b_c);
        __syncthreads();
#pragma unroll
        for (int k = 0; k < 16; k++) {
            const float4 a4 = *(const float4*)&As[k][tr];
            const float4 b4 = *(const float4*)&Bs[k][tc];
            acc[0][0] = fmaf(a4.x, b4.x, acc[0][0]);
            acc[0][1] = fmaf(a4.x, b4.y, acc[0][1]);
            acc[0][2] = fmaf(a4.x, b4.z, acc[0][2]);
            acc[0][3] = fmaf(a4.x, b4.w, acc[0][3]);
            acc[1][0] = fmaf(a4.y, b4.x, acc[1][0]);
            acc[1][1] = fmaf(a4.y, b4.y, acc[1][1]);
            acc[1][2] = fmaf(a4.y, b4.z, acc[1][2]);
            acc[1][3] = fmaf(a4.y, b4.w, acc[1][3]);
            acc[2][0] = fmaf(a4.z, b4.x, acc[2][0]);
            acc[2][1] = fmaf(a4.z, b4.y, acc[2][1]);
            acc[2][2] = fmaf(a4.z, b4.z, acc[2][2]);
            acc[2][3] = fmaf(a4.z, b4.w, acc[2][3]);
            acc[3][0] = fmaf(a4.w, b4.x, acc[3][0]);
            acc[3][1] = fmaf(a4.w, b4.y, acc[3][1]);
            acc[3][2] = fmaf(a4.w, b4.z, acc[3][2]);
            acc[3][3] = fmaf(a4.w, b4.w, acc[3][3]);
        }
        __syncthreads();
    }
#pragma unroll
    for (int i = 0; i < 4; i++) {
        const int r = brow + tr + i;
        if (r >= M) continue;
        float4 o;
        o.x = acc[i][0] + bias[bcol + tc + 0];
        o.y = acc[i][1] + bias[bcol + tc + 1];
        o.z = acc[i][2] + bias[bcol + tc + 2];
        o.w = acc[i][3] + bias[bcol + tc + 3];
        *(float4*)(C + (size_t)r * N + bcol + tc) = o;
    }
}

// ---------------- gate logits: z = x @ w_enc + b_enc (sigmoid skipped: monotonic) ----
__global__ void scores_k(const float* __restrict__ x, const float* __restrict__ w,
                         const float* __restrict__ be, float* __restrict__ sc)
{
    const int warp = (blockIdx.x * blockDim.x + threadIdx.x) >> 5;
    const int lane = threadIdx.x & 31;
    if (warp >= B_ * N_) return;
    const float* row = x + (size_t)warp * HID;
    float s = 0.f;
    for (int k = lane; k < HID; k += 32) s = fmaf(row[k], w[k], s);
#pragma unroll
    for (int o = 16; o; o >>= 1) s += __shfl_down_sync(0xffffffffu, s, o);
    if (lane == 0) sc[warp] = s + be[0];
}

// ---------------- top-16 per batch (iterative argmax, tie -> lower index) --------
__global__ void topk_k(const float* __restrict__ sc, int* __restrict__ tk)
{
    const int b = blockIdx.x;
    const float* s = sc + b * N_;
    __shared__ float sv[256];
    __shared__ int   si[256];
    __shared__ int   sel[TOPK];
    for (int r = 0; r < TOPK; r++) {
        float best = -FLT_MAX;
        int   bi   = 0x7fffffff;
        for (int i = threadIdx.x; i < N_; i += 256) {
            bool skip = false;
            for (int t = 0; t < r; t++) if (sel[t] == i) skip = true;
            if (skip) continue;
            const float vv = s[i];
            if (vv > best || (vv == best && i < bi)) { best = vv; bi = i; }
        }
        sv[threadIdx.x] = best; si[threadIdx.x] = bi;
        __syncthreads();
        for (int t = 128; t; t >>= 1) {
            if (threadIdx.x < t) {
                if (sv[threadIdx.x + t] > sv[threadIdx.x] ||
                    (sv[threadIdx.x + t] == sv[threadIdx.x] &&
                     si[threadIdx.x + t] < si[threadIdx.x])) {
                    sv[threadIdx.x] = sv[threadIdx.x + t];
                    si[threadIdx.x] = si[threadIdx.x + t];
                }
            }
            __syncthreads();
        }
        if (threadIdx.x == 0) sel[r] = si[0];
        __syncthreads();
    }
    if (threadIdx.x < TOPK) tk[b * TOPK + threadIdx.x] = sel[threadIdx.x];
}

// ---------------- Q = mean of top-k rows of (pre-relu) x -------------------------
__global__ void qmean_k(const float* __restrict__ x, const int* __restrict__ tk,
                        float* __restrict__ Q)
{
    const int b = blockIdx.x, c = threadIdx.x;
    float s = 0.f;
    for (int t = 0; t < TOPK; t++) {
        const int idx = tk[b * TOPK + t];
        s += x[((size_t)(b * N_ + idx)) * HID + c];
    }
    Q[b * HID + c] = s * (1.f / TOPK);
}

// ---------------- x = relu(x - Q[b]) in place ------------------------------------
__global__ void relu_k(float* __restrict__ x, const float* __restrict__ Q)
{
    const int i = blockIdx.x * blockDim.x + threadIdx.x;
    if (i >= B_ * N_ * HID) return;
    const int c = i & (HID - 1);
    const int b = i / (N_ * HID);
    x[i] = fmaxf(x[i] - Q[b * HID + c], 0.f);
}

// ---------------- depthwise 3x3 conv (SAME) + bias + residual -> x3 rows 1.. -----
// padded row m>=8192 aliases relu'd row m-8192 (concat of x[:, :89]).
__global__ void conv_k(const float* __restrict__ x, const float* __restrict__ cw,
                       const float* __restrict__ cb, float* __restrict__ x3)
{
    const int i = blockIdx.x * blockDim.x + threadIdx.x;
    if (i >= B_ * NPAD * HID) return;
    const int c = i & (HID - 1);
    const int n = (i >> 9) % NPAD;
    const int b = i / (NPAD * HID);
    const int pi = n / HH, pj = n % HH;
    const float* xb = x + (size_t)b * N_ * HID;
    float acc = 0.f, center = 0.f;
#pragma unroll
    for (int di = 0; di < 3; di++) {
        const int ii = pi + di - 1;
        if (ii < 0 || ii >= HH) continue;
#pragma unroll
        for (int dj = 0; dj < 3; dj++) {
            const int jj = pj + dj - 1;
            if (jj < 0 || jj >= HH) continue;
            int m = ii * HH + jj;
            if (m >= N_) m -= N_;
            const float vv = xb[(size_t)m * HID + c];
            acc = fmaf(vv, cw[c * 9 + di * 3 + dj], acc);
            if (di == 1 && dj == 1) center = vv;
        }
    }
    x3[((size_t)b * NTOK + n + 1) * HID + c] = acc + cb[c] + center;
}

// ---------------- cls token -> x3 row 0 ------------------------------------------
__global__ void cls_k(const float* __restrict__ cls, float* __restrict__ x3)
{
    x3[((size_t)blockIdx.x * NTOK) * HID + threadIdx.x] = cls[threadIdx.x];
}

// ---------------- tiny row GEMM: Y[b,:] = X[b,:] @ W (HIDxHID) + bias ------------
__global__ void rowmat_k(const float* __restrict__ X, const float* __restrict__ W,
                         const float* __restrict__ bias, float* __restrict__ Y)
{
    const int b = blockIdx.x, c = threadIdx.x;
    __shared__ float xr[HID];
    xr[c] = X[b * HID + c];
    __syncthreads();
    float s = bias[c];
    for (int k = 0; k < HID; k++) s = fmaf(xr[k], W[k * HID + c], s);
    Y[b * HID + c] = s;
}

// ---------------- attention logits: q . k / sqrt(HID) ----------------------------
__global__ void logits_k(const float* __restrict__ q, const float* __restrict__ kk,
                         float* __restrict__ logits)
{
    const int bh = blockIdx.x;
    const int b = bh >> 3, h = bh & 7;
    __shared__ float qs[DH];
    if (threadIdx.x < DH) qs[threadIdx.x] = q[b * HID + h * DH + threadIdx.x];
    __syncthreads();
    const int k = blockIdx.y * blockDim.x + threadIdx.x;
    if (k >= NTOK) return;
    const float* kp = kk + ((size_t)(b * NTOK + k)) * HID + h * DH;
    float s = 0.f;
#pragma unroll
    for (int d2 = 0; d2 < DH; d2 += 4) {
        const float4 kv = *(const float4*)(kp + d2);
        s = fmaf(qs[d2 + 0], kv.x, s);
        s = fmaf(qs[d2 + 1], kv.y, s);
        s = fmaf(qs[d2 + 2], kv.z, s);
        s = fmaf(qs[d2 + 3], kv.w, s);
    }
    logits[bh * NTOK + k] = s * 0.04419417382415922f;  // 1/sqrt(512)
}

// ---------------- softmax stats (max, sumexp) per (b,h) --------------------------
__global__ void stats_k(const float* __restrict__ logits, float* __restrict__ stats)
{
    const int bh = blockIdx.x;
    const float* lg = logits + bh * NTOK;
    __shared__ float red[256];
    float mx = -FLT_MAX;
    for (int k = threadIdx.x; k < NTOK; k += 256) mx = fmaxf(mx, lg[k]);
    red[threadIdx.x] = mx; __syncthreads();
    for (int s = 128; s; s >>= 1) {
        if (threadIdx.x < s) red[threadIdx.x] = fmaxf(red[threadIdx.x], red[threadIdx.x + s]);
        __syncthreads();
    }
    mx = red[0]; __syncthreads();
    float sm = 0.f;
    for (int k = threadIdx.x; k < NTOK; k += 256) sm += expf(lg[k] - mx);
    red[threadIdx.x] = sm; __syncthreads();
    for (int s = 128; s; s >>= 1) {
        if (threadIdx.x < s) red[threadIdx.x] += red[threadIdx.x + s];
        __syncthreads();
    }
    if (threadIdx.x == 0) { stats[bh * 2] = mx; stats[bh * 2 + 1] = red[0]; }
}

// ---------------- O = q + softmax(logits) @ v ------------------------------------
__global__ void attno_k(const float* __restrict__ logits, const float* __restrict__ stats,
                        const float* __restrict__ v, const float* __restrict__ q,
                        float* __restrict__ O)
{
    const int bh = blockIdx.x;
    const int b = bh >> 3, h = bh & 7;
    const float mx = stats[bh * 2];
    const float inv_den = 1.f / stats[bh * 2 + 1];
    const int d  = threadIdx.x & 63;
    const int kg = threadIdx.x >> 6;  // 0..3
    float acc = 0.f;
    for (int k = kg; k < NTOK; k += 4) {
        const float w = expf(logits[bh * NTOK + k] - mx);
        acc = fmaf(w, v[((size_t)(b * NTOK + k)) * HID + h * DH + d], acc);
    }
    __shared__ float red[256];
    red[threadIdx.x] = acc; __syncthreads();
    if (kg == 0) {
        acc = red[d] + red[64 + d] + red[128 + d] + red[192 + d];
        O[b * HID + h * DH + d] = q[b * HID + h * DH + d] + acc * inv_den;
    }
}

// ---------------- O += relu(O @ Wo + bo) -----------------------------------------
__global__ void otrans_k(const float* __restrict__ Wo, const float* __restrict__ bo,
                         float* __restrict__ O)
{
    const int b = blockIdx.x, c = threadIdx.x;
    __shared__ float orow[HID];
    orow[c] = O[b * HID + c];
    __syncthreads();
    float s = bo[c];
    for (int k = 0; k < HID; k++) s = fmaf(orow[k], Wo[k * HID + c], s);
    O[b * HID + c] = orow[c] + fmaxf(s, 0.f);
}

// ---------------- out = O @ Wc + bc ----------------------------------------------
__global__ void final_k(const float* __restrict__ O, const float* __restrict__ Wc,
                        const float* __restrict__ bc, float* __restrict__ out)
{
    const int b = blockIdx.x >> 1, j = blockIdx.x & 1;
    __shared__ float red[128];
    float s = 0.f;
    for (int c = threadIdx.x; c < HID; c += 128) s = fmaf(O[b * HID + c], Wc[c * NCLS + j], s);
    red[threadIdx.x] = s; __syncthreads();
    for (int t = 64; t; t >>= 1) {
        if (threadIdx.x < t) red[threadIdx.x] += red[threadIdx.x + t];
        __syncthreads();
    }
    if (threadIdx.x == 0) out[b * NCLS + j] = red[0] + bc[j];
}

// =================================================================================
extern "C" void kernel_launch(void* const* d_in, const int* in_sizes, int n_in,
                              void* d_out, int out_size)
{
    const float* inputs = (const float*)d_in[0];
    const float* W_feat = (const float*)d_in[1];
    const float* b_feat = (const float*)d_in[2];
    const float* w_enc  = (const float*)d_in[3];
    const float* b_enc  = (const float*)d_in[4];
    const float* cls    = (const float*)d_in[5];
    const float* conv_w = (const float*)d_in[6];
    const float* conv_b = (const float*)d_in[7];
    const float* Wq     = (const float*)d_in[8];
    const float* bq     = (const float*)d_in[9];
    const float* Wk     = (const float*)d_in[10];
    const float* bk     = (const float*)d_in[11];
    const float* Wv     = (const float*)d_in[12];
    const float* bv     = (const float*)d_in[13];
    const float* Wo     = (const float*)d_in[14];
    const float* bo     = (const float*)d_in[15];
    const float* Wc     = (const float*)d_in[16];
    const float* bc     = (const float*)d_in[17];
    float* out = (float*)d_out;
    (void)in_sizes; (void)n_in; (void)out_size;

    float *x, *scores, *Q, *x3, *kk, *v, *q, *logits, *stats, *O;
    int* topk;
    cudaGetSymbolAddress((void**)&x,      g_x);
    cudaGetSymbolAddress((void**)&scores, g_scores);
    cudaGetSymbolAddress((void**)&topk,   g_topk);
    cudaGetSymbolAddress((void**)&Q,      g_Q);
    cudaGetSymbolAddress((void**)&x3,     g_x3);
    cudaGetSymbolAddress((void**)&kk,     g_kk);
    cudaGetSymbolAddress((void**)&v,      g_v);
    cudaGetSymbolAddress((void**)&q,      g_q);
    cudaGetSymbolAddress((void**)&logits, g_logits);
    cudaGetSymbolAddress((void**)&stats,  g_stats);
    cudaGetSymbolAddress((void**)&O,      g_O);

    // 1. x = inputs @ W_feat + b_feat   (32768 x 1024 x 512)
    sgemm_bias<<<dim3(HID / 64, (B_ * N_ + 63) / 64), 256>>>(
        inputs, W_feat, b_feat, x, B_ * N_, HID, IND);
    // 2. gate logits (pre-sigmoid; sigmoid is monotonic -> same top-k)
    scores_k<<<(B_ * N_) / 8, 256>>>(x, w_enc, b_enc, scores);
    // 3. top-16 per batch
    topk_k<<<B_, 256>>>(scores, topk);
    // 4. Q = mean of selected (pre-relu) rows
    qmean_k<<<B_, HID>>>(x, topk, Q);
    // 5. x = relu(x - Q) in place
    relu_k<<<(B_ * N_ * HID + 255) / 256, 256>>>(x, Q);
    // 6. depthwise conv + residual -> x3 rows 1..8281
    conv_k<<<(B_ * NPAD * HID + 255) / 256, 256>>>(x, conv_w, conv_b, x3);
    // 7. cls token -> x3 row 0
    cls_k<<<B_, HID>>>(cls, x3);
    // 8/9. K,V projections  (33128 x 512 x 512 each)
    sgemm_bias<<<dim3(HID / 64, (B_ * NTOK + 63) / 64), 256>>>(
        x3, Wk, bk, kk, B_ * NTOK, HID, HID);
    sgemm_bias<<<dim3(HID / 64, (B_ * NTOK + 63) / 64), 256>>>(
        x3, Wv, bv, v, B_ * NTOK, HID, HID);
    // 10. q = Q @ Wq + bq
    rowmat_k<<<B_, HID>>>(Q, Wq, bq, q);
    // 11. attention logits
    logits_k<<<dim3(B_ * HEADS, (NTOK + 255) / 256), 256>>>(q, kk, logits);
    // 12. softmax stats
    stats_k<<<B_ * HEADS, 256>>>(logits, stats);
    // 13. O = q + A @ v
    attno_k<<<B_ * HEADS, 256>>>(logits, stats, v, q, O);
    // 14. O += relu(O @ Wo + bo)
    otrans_k<<<B_, HID>>>(Wo, bo, O);
    // 15. out = O @ Wc + bc
    final_k<<<B_ * NCLS, 128>>>(O, Wc, bc, out);
}

// round 2
// speedup vs baseline: 1.2384x; 1.2384x over previous
#include <cuda_runtime.h>
#include <math.h>
#include <float.h>
#include <stdint.h>

#define B_    4
#define N_    8192
#define IND   1024
#define HID   512
#define HEADS 8
#define TOPK  16
#define NCLS  2
#define HH    91
#define NPAD  8281   /* HH*HH */
#define NTOK  8282   /* NPAD + 1 cls */
#define DH    64     /* HID/HEADS */

// ---------------- scratch (no allocations allowed) ----------------
__device__ __align__(128) float g_x[B_ * N_ * HID];        // feat GEMM out (pre-relu, tf32-accurate)
__device__ __align__(128) float g_u[IND + 1];               // folded enc vector + fused bias const
__device__ __align__(128) float g_scores[B_ * N_];          // pre-sigmoid gate logits (fp32-exact)
__device__ __align__(128) int   g_topk[B_ * TOPK];
__device__ __align__(128) float g_Q[B_ * HID];
__device__ __align__(128) float g_x3[B_ * NTOK * HID];      // cls + conv-residual tokens
__device__ __align__(128) float g_kk[B_ * NTOK * HID];
__device__ __align__(128) float g_v [B_ * NTOK * HID];
__device__ __align__(128) float g_q [B_ * HID];
__device__ __align__(128) float g_logits[B_ * HEADS * NTOK];
__device__ __align__(128) float g_stats[B_ * HEADS * 2];
__device__ __align__(128) float g_O [B_ * HID];

// ---------------- tf32 helpers ----------------
__device__ __forceinline__ uint32_t f2tf(float x) {
    uint32_t r;
    asm("cvt.rna.tf32.f32 %0, %1;" : "=r"(r) : "f"(x));
    return r;
}
__device__ __forceinline__ void mma8(float* c, const uint32_t* a, const uint32_t* b) {
    asm volatile(
        "mma.sync.aligned.m16n8k8.row.col.f32.tf32.tf32.f32 "
        "{%0,%1,%2,%3}, {%4,%5,%6,%7}, {%8,%9}, {%0,%1,%2,%3};"
        : "+f"(c[0]), "+f"(c[1]), "+f"(c[2]), "+f"(c[3])
        : "r"(a[0]), "r"(a[1]), "r"(a[2]), "r"(a[3]), "r"(b[0]), "r"(b[1]));
}

// ---------------- tf32 tensor-core GEMM: C = A(MxK) @ B(KxN) + bias -------------
// CTA tile 128x64, BK=32, 256 threads (8 warps, 4x2 warp grid, 32x32 warp tile).
__global__ void __launch_bounds__(256) tf32_gemm_bias(
    const float* __restrict__ A, const float* __restrict__ Bm,
    const float* __restrict__ bias, float* __restrict__ C,
    int M, int N, int K)
{
    __shared__ uint32_t As[32][132];  // [k][m], padded
    __shared__ uint32_t Bs[32][68];   // [k][n], padded

    const int tid  = threadIdx.x;
    const int warp = tid >> 5, lane = tid & 31;
    const int bm = blockIdx.y * 128, bn = blockIdx.x * 64;
    const int wm = (warp >> 1) * 32, wn = (warp & 1) * 32;
    const int lr = lane >> 2, lc = lane & 3;

    float acc[2][4][4] = {};

    const int a_c4 = (tid & 7) * 4;    // k offset within tile (A row-major: contiguous in k)
    const int a_r0 = tid >> 3;         // m row 0..31, +32*i
    const int b_c4 = (tid & 15) * 4;   // n offset
    const int b_r0 = tid >> 4;         // k row 0..15, +16*i

    for (int k0 = 0; k0 < K; k0 += 32) {
#pragma unroll
        for (int i = 0; i < 4; i++) {
            const int r = a_r0 + i * 32;
            const int gr = bm + r;
            float4 v = make_float4(0.f, 0.f, 0.f, 0.f);
            if (gr < M) v = *(const float4*)(A + (size_t)gr * K + k0 + a_c4);
            As[a_c4 + 0][r] = f2tf(v.x);
            As[a_c4 + 1][r] = f2tf(v.y);
            As[a_c4 + 2][r] = f2tf(v.z);
            As[a_c4 + 3][r] = f2tf(v.w);
        }
#pragma unroll
        for (int i = 0; i < 2; i++) {
            const int kr = b_r0 + i * 16;
            const float4 v = *(const float4*)(Bm + (size_t)(k0 + kr) * N + bn + b_c4);
            Bs[kr][b_c4 + 0] = f2tf(v.x);
            Bs[kr][b_c4 + 1] = f2tf(v.y);
            Bs[kr][b_c4 + 2] = f2tf(v.z);
            Bs[kr][b_c4 + 3] = f2tf(v.w);
        }
        __syncthreads();
#pragma unroll
        for (int ks = 0; ks < 4; ks++) {
            const int kb = ks * 8;
            uint32_t a[2][4], b[4][2];
#pragma unroll
            for (int mi = 0; mi < 2; mi++) {
                const int m = wm + mi * 16 + lr;
                a[mi][0] = As[kb + lc][m];
                a[mi][1] = As[kb + lc][m + 8];
                a[mi][2] = As[kb + lc + 4][m];
                a[mi][3] = As[kb + lc + 4][m + 8];
            }
#pragma unroll
            for (int ni = 0; ni < 4; ni++) {
                const int n = wn + ni * 8 + lr;
                b[ni][0] = Bs[kb + lc][n];
                b[ni][1] = Bs[kb + lc + 4][n];
            }
#pragma unroll
            for (int mi = 0; mi < 2; mi++)
#pragma unroll
                for (int ni = 0; ni < 4; ni++)
                    mma8(acc[mi][ni], a[mi], b[ni]);
        }
        __syncthreads();
    }

#pragma unroll
    for (int mi = 0; mi < 2; mi++) {
#pragma unroll
        for (int ni = 0; ni < 4; ni++) {
            const int r0 = bm + wm + mi * 16 + lr;
            const int cc = bn + wn + ni * 8 + lc * 2;
            const float bx = bias[cc], by = bias[cc + 1];
            if (r0 < M) {
                C[(size_t)r0 * N + cc]     = acc[mi][ni][0] + bx;
                C[(size_t)r0 * N + cc + 1] = acc[mi][ni][1] + by;
            }
            if (r0 + 8 < M) {
                C[(size_t)(r0 + 8) * N + cc]     = acc[mi][ni][2] + bx;
                C[(size_t)(r0 + 8) * N + cc + 1] = acc[mi][ni][3] + by;
            }
        }
    }
}

// ---------------- fold: u = W_feat @ w_enc (fp32 exact path for gating) ----------
__global__ void fold_enc_k(const float* __restrict__ W_feat, const float* __restrict__ w_enc,
                           float* __restrict__ u)
{
    const int warp = (blockIdx.x * blockDim.x + threadIdx.x) >> 5;
    const int lane = threadIdx.x & 31;
    if (warp >= IND) return;
    const float* row = W_feat + (size_t)warp * HID;
    float s = 0.f;
    for (int k = lane; k < HID; k += 32) s = fmaf(row[k], w_enc[k], s);
#pragma unroll
    for (int o = 16; o; o >>= 1) s += __shfl_down_sync(0xffffffffu, s, o);
    if (lane == 0) u[warp] = s;
}
__global__ void fold_const_k(const float* __restrict__ b_feat, const float* __restrict__ w_enc,
                             const float* __restrict__ b_enc, float* __restrict__ u)
{
    __shared__ float red[512];
    float s = b_feat[threadIdx.x] * w_enc[threadIdx.x];
    red[threadIdx.x] = s; __syncthreads();
    for (int t = 256; t; t >>= 1) {
        if (threadIdx.x < t) red[threadIdx.x] += red[threadIdx.x + t];
        __syncthreads();
    }
    if (threadIdx.x == 0) u[IND] = red[0] + b_enc[0];
}

// ---------------- gate logits from raw inputs (fp32, protects top-k) -------------
__global__ void scores_k(const float* __restrict__ inp, const float* __restrict__ u,
                         float* __restrict__ sc)
{
    const int warp = (blockIdx.x * blockDim.x + threadIdx.x) >> 5;
    const int lane = threadIdx.x & 31;
    if (warp >= B_ * N_) return;
    const float* row = inp + (size_t)warp * IND;
    float s = 0.f;
#pragma unroll 8
    for (int k = lane; k < IND; k += 32) s = fmaf(row[k], u[k], s);
#pragma unroll
    for (int o = 16; o; o >>= 1) s += __shfl_down_sync(0xffffffffu, s, o);
    if (lane == 0) sc[warp] = s + u[IND];
}

// ---------------- top-16 per batch (iterative argmax, tie -> lower index) --------
__global__ void topk_k(const float* __restrict__ sc, int* __restrict__ tk)
{
    const int b = blockIdx.x;
    const float* s = sc + b * N_;
    __shared__ float sv[256];
    __shared__ int   si[256];
    __shared__ int   sel[TOPK];
    for (int r = 0; r < TOPK; r++) {
        float best = -FLT_MAX;
        int   bi   = 0x7fffffff;
        for (int i = threadIdx.x; i < N_; i += 256) {
            bool skip = false;
            for (int t = 0; t < r; t++) if (sel[t] == i) skip = true;
            if (skip) continue;
            const float vv = s[i];
            if (vv > best || (vv == best && i < bi)) { best = vv; bi = i; }
        }
        sv[threadIdx.x] = best; si[threadIdx.x] = bi;
        __syncthreads();
        for (int t = 128; t; t >>= 1) {
            if (threadIdx.x < t) {
                if (sv[threadIdx.x + t] > sv[threadIdx.x] ||
                    (sv[threadIdx.x + t] == sv[threadIdx.x] &&
                     si[threadIdx.x + t] < si[threadIdx.x])) {
                    sv[threadIdx.x] = sv[threadIdx.x + t];
                    si[threadIdx.x] = si[threadIdx.x + t];
                }
            }
            __syncthreads();
        }
        if (threadIdx.x == 0) sel[r] = si[0];
        __syncthreads();
    }
    if (threadIdx.x < TOPK) tk[b * TOPK + threadIdx.x] = sel[threadIdx.x];
}

// ---------------- Q = mean of top-k rows of (pre-relu) x -------------------------
__global__ void qmean_k(const float* __restrict__ x, const int* __restrict__ tk,
                        float* __restrict__ Q)
{
    const int b = blockIdx.x, c = threadIdx.x;
    float s = 0.f;
    for (int t = 0; t < TOPK; t++) {
        const int idx = tk[b * TOPK + t];
        s += x[((size_t)(b * N_ + idx)) * HID + c];
    }
    Q[b * HID + c] = s * (1.f / TOPK);
}

// ---------------- fused relu + depthwise 3x3 conv + bias + residual --------------
// reads pre-relu x, applies relu(x - Q) per tap; row m>=N_ wraps to m-N_.
__global__ void conv_k(const float* __restrict__ x, const float* __restrict__ Q,
                       const float* __restrict__ cw, const float* __restrict__ cb,
                       float* __restrict__ x3)
{
    const int i = blockIdx.x * blockDim.x + threadIdx.x;
    if (i >= B_ * NPAD * HID) return;
    const int c = i & (HID - 1);
    const int n = (i >> 9) % NPAD;
    const int b = i / (NPAD * HID);
    const int pi = n / HH, pj = n % HH;
    const float* xb = x + (size_t)b * N_ * HID;
    const float qc = Q[b * HID + c];
    float acc = 0.f, center = 0.f;
#pragma unroll
    for (int di = 0; di < 3; di++) {
        const int ii = pi + di - 1;
        if (ii < 0 || ii >= HH) continue;
#pragma unroll
        for (int dj = 0; dj < 3; dj++) {
            const int jj = pj + dj - 1;
            if (jj < 0 || jj >= HH) continue;
            int m = ii * HH + jj;
            if (m >= N_) m -= N_;
            const float vv = fmaxf(xb[(size_t)m * HID + c] - qc, 0.f);
            acc = fmaf(vv, cw[c * 9 + di * 3 + dj], acc);
            if (di == 1 && dj == 1) center = vv;
        }
    }
    x3[((size_t)b * NTOK + n + 1) * HID + c] = acc + cb[c] + center;
}

// ---------------- cls token -> x3 row 0 ------------------------------------------
__global__ void cls_k(const float* __restrict__ cls, float* __restrict__ x3)
{
    x3[((size_t)blockIdx.x * NTOK) * HID + threadIdx.x] = cls[threadIdx.x];
}

// ---------------- tiny row GEMM: Y[b,:] = X[b,:] @ W (HIDxHID) + bias ------------
__global__ void rowmat_k(const float* __restrict__ X, const float* __restrict__ W,
                         const float* __restrict__ bias, float* __restrict__ Y)
{
    const int b = blockIdx.x, c = threadIdx.x;
    __shared__ float xr[HID];
    xr[c] = X[b * HID + c];
    __syncthreads();
    float s = bias[c];
    for (int k = 0; k < HID; k++) s = fmaf(xr[k], W[k * HID + c], s);
    Y[b * HID + c] = s;
}

// ---------------- attention logits: q . k / sqrt(HID) ----------------------------
__global__ void logits_k(const float* __restrict__ q, const float* __restrict__ kk,
                         float* __restrict__ logits)
{
    const int bh = blockIdx.x;
    const int b = bh >> 3, h = bh & 7;
    __shared__ float qs[DH];
    if (threadIdx.x < DH) qs[threadIdx.x] = q[b * HID + h * DH + threadIdx.x];
    __syncthreads();
    const int k = blockIdx.y * blockDim.x + threadIdx.x;
    if (k >= NTOK) return;
    const float* kp = kk + ((size_t)(b * NTOK + k)) * HID + h * DH;
    float s = 0.f;
#pragma unroll
    for (int d2 = 0; d2 < DH; d2 += 4) {
        const float4 kv = *(const float4*)(kp + d2);
        s = fmaf(qs[d2 + 0], kv.x, s);
        s = fmaf(qs[d2 + 1], kv.y, s);
        s = fmaf(qs[d2 + 2], kv.z, s);
        s = fmaf(qs[d2 + 3], kv.w, s);
    }
    logits[bh * NTOK + k] = s * 0.04419417382415922f;  // 1/sqrt(512)
}

// ---------------- softmax stats (max, sumexp) per (b,h) --------------------------
__global__ void stats_k(const float* __restrict__ logits, float* __restrict__ stats)
{
    const int bh = blockIdx.x;
    const float* lg = logits + bh * NTOK;
    __shared__ float red[256];
    float mx = -FLT_MAX;
    for (int k = threadIdx.x; k < NTOK; k += 256) mx = fmaxf(mx, lg[k]);
    red[threadIdx.x] = mx; __syncthreads();
    for (int s = 128; s; s >>= 1) {
        if (threadIdx.x < s) red[threadIdx.x] = fmaxf(red[threadIdx.x], red[threadIdx.x + s]);
        __syncthreads();
    }
    mx = red[0]; __syncthreads();
    float sm = 0.f;
    for (int k = threadIdx.x; k < NTOK; k += 256) sm += expf(lg[k] - mx);
    red[threadIdx.x] = sm; __syncthreads();
    for (int s = 128; s; s >>= 1) {
        if (threadIdx.x < s) red[threadIdx.x] += red[threadIdx.x + s];
        __syncthreads();
    }
    if (threadIdx.x == 0) { stats[bh * 2] = mx; stats[bh * 2 + 1] = red[0]; }
}

// ---------------- O = q + softmax(logits) @ v ------------------------------------
__global__ void attno_k(const float* __restrict__ logits, const float* __restrict__ stats,
                        const float* __restrict__ v, const float* __restrict__ q,
                        float* __restrict__ O)
{
    const int bh = blockIdx.x;
    const int b = bh >> 3, h = bh & 7;
    const float mx = stats[bh * 2];
    const float inv_den = 1.f / stats[bh * 2 + 1];
    const int d  = threadIdx.x & 63;
    const int kg = threadIdx.x >> 6;  // 0..3
    float acc = 0.f;
    for (int k = kg; k < NTOK; k += 4) {
        const float w = expf(logits[bh * NTOK + k] - mx);
        acc = fmaf(w, v[((size_t)(b * NTOK + k)) * HID + h * DH + d], acc);
    }
    __shared__ float red[256];
    red[threadIdx.x] = acc; __syncthreads();
    if (kg == 0) {
        acc = red[d] + red[64 + d] + red[128 + d] + red[192 + d];
        O[b * HID + h * DH + d] = q[b * HID + h * DH + d] + acc * inv_den;
    }
}

// ---------------- O += relu(O @ Wo + bo) -----------------------------------------
__global__ void otrans_k(const float* __restrict__ Wo, const float* __restrict__ bo,
                         float* __restrict__ O)
{
    const int b = blockIdx.x, c = threadIdx.x;
    __shared__ float orow[HID];
    orow[c] = O[b * HID + c];
    __syncthreads();
    float s = bo[c];
    for (int k = 0; k < HID; k++) s = fmaf(orow[k], Wo[k * HID + c], s);
    O[b * HID + c] = orow[c] + fmaxf(s, 0.f);
}

// ---------------- out = O @ Wc + bc ----------------------------------------------
__global__ void final_k(const float* __restrict__ O, const float* __restrict__ Wc,
                        const float* __restrict__ bc, float* __restrict__ out)
{
    const int b = blockIdx.x >> 1, j = blockIdx.x & 1;
    __shared__ float red[128];
    float s = 0.f;
    for (int c = threadIdx.x; c < HID; c += 128) s = fmaf(O[b * HID + c], Wc[c * NCLS + j], s);
    red[threadIdx.x] = s; __syncthreads();
    for (int t = 64; t; t >>= 1) {
        if (threadIdx.x < t) red[threadIdx.x] += red[threadIdx.x + t];
        __syncthreads();
    }
    if (threadIdx.x == 0) out[b * NCLS + j] = red[0] + bc[j];
}

// =================================================================================
extern "C" void kernel_launch(void* const* d_in, const int* in_sizes, int n_in,
                              void* d_out, int out_size)
{
    const float* inputs = (const float*)d_in[0];
    const float* W_feat = (const float*)d_in[1];
    const float* b_feat = (const float*)d_in[2];
    const float* w_enc  = (const float*)d_in[3];
    const float* b_enc  = (const float*)d_in[4];
    const float* cls    = (const float*)d_in[5];
    const float* conv_w = (const float*)d_in[6];
    const float* conv_b = (const float*)d_in[7];
    const float* Wq     = (const float*)d_in[8];
    const float* bq     = (const float*)d_in[9];
    const float* Wk     = (const float*)d_in[10];
    const float* bk     = (const float*)d_in[11];
    const float* Wv     = (const float*)d_in[12];
    const float* bv     = (const float*)d_in[13];
    const float* Wo     = (const float*)d_in[14];
    const float* bo     = (const float*)d_in[15];
    const float* Wc     = (const float*)d_in[16];
    const float* bc     = (const float*)d_in[17];
    float* out = (float*)d_out;
    (void)in_sizes; (void)n_in; (void)out_size;

    float *x, *u, *scores, *Q, *x3, *kk, *v, *q, *logits, *stats, *O;
    int* topk;
    cudaGetSymbolAddress((void**)&x,      g_x);
    cudaGetSymbolAddress((void**)&u,      g_u);
    cudaGetSymbolAddress((void**)&scores, g_scores);
    cudaGetSymbolAddress((void**)&topk,   g_topk);
    cudaGetSymbolAddress((void**)&Q,      g_Q);
    cudaGetSymbolAddress((void**)&x3,     g_x3);
    cudaGetSymbolAddress((void**)&kk,     g_kk);
    cudaGetSymbolAddress((void**)&v,      g_v);
    cudaGetSymbolAddress((void**)&q,      g_q);
    cudaGetSymbolAddress((void**)&logits, g_logits);
    cudaGetSymbolAddress((void**)&stats,  g_stats);
    cudaGetSymbolAddress((void**)&O,      g_O);

    // 0. fold enc weights for fp32-exact gating path
    fold_enc_k<<<IND / 8, 256>>>(W_feat, w_enc, u);
    fold_const_k<<<1, 512>>>(b_feat, w_enc, b_enc, u);
    // 1. x = inputs @ W_feat + b_feat  (tf32 tensor cores, 32768x512x1024)
    tf32_gemm_bias<<<dim3(HID / 64, (B_ * N_ + 127) / 128), 256>>>(
        inputs, W_feat, b_feat, x, B_ * N_, HID, IND);
    // 2. gate logits from raw inputs (fp32 exact; sigmoid monotone -> same ranking)
    scores_k<<<(B_ * N_) / 8, 256>>>(inputs, u, scores);
    // 3. top-16 per batch
    topk_k<<<B_, 256>>>(scores, topk);
    // 4. Q = mean of selected (pre-relu) rows
    qmean_k<<<B_, HID>>>(x, topk, Q);
    // 5+6. fused relu + depthwise conv + residual -> x3 rows 1..8281
    conv_k<<<(B_ * NPAD * HID + 255) / 256, 256>>>(x, Q, conv_w, conv_b, x3);
    // 7. cls token -> x3 row 0
    cls_k<<<B_, HID>>>(cls, x3);
    // 8/9. K,V projections (tf32 tensor cores, 33128x512x512 each)
    tf32_gemm_bias<<<dim3(HID / 64, (B_ * NTOK + 127) / 128), 256>>>(
        x3, Wk, bk, kk, B_ * NTOK, HID, HID);
    tf32_gemm_bias<<<dim3(HID / 64, (B_ * NTOK + 127) / 128), 256>>>(
        x3, Wv, bv, v, B_ * NTOK, HID, HID);
    // 10. q = Q @ Wq + bq
    rowmat_k<<<B_, HID>>>(Q, Wq, bq, q);
    // 11. attention logits
    logits_k<<<dim3(B_ * HEADS, (NTOK + 255) / 256), 256>>>(q, kk, logits);
    // 12. softmax stats
    stats_k<<<B_ * HEADS, 256>>>(logits, stats);
    // 13. O = q + A @ v
    attno_k<<<B_ * HEADS, 256>>>(logits, stats, v, q, O);
    // 14. O += relu(O @ Wo + bo)
    otrans_k<<<B_, HID>>>(Wo, bo, O);
    // 15. out = O @ Wc + bc
    final_k<<<B_ * NCLS, 128>>>(O, Wc, bc, out);
}

// round 5
// speedup vs baseline: 1.6359x; 1.3210x over previous
#include <cuda_runtime.h>
#include <math.h>
#include <float.h>
#include <stdint.h>

#define B_    4
#define N_    8192
#define IND   1024
#define HID   512
#define HEADS 8
#define TOPK  16
#define NCLS  2
#define HH    91
#define NPAD  8281   /* HH*HH */
#define NTOK  8282   /* NPAD + 1 cls */
#define DH    64     /* HID/HEADS */

// ---------------- scratch (no allocations allowed) ----------------
__device__ __align__(128) float    g_x[B_ * N_ * HID];      // GEMM1 out (fp32)
__device__ __align__(128) uint32_t g_At[B_ * N_ * IND];     // inputs pre-converted to tf32
__device__ __align__(128) uint32_t g_Bt[HID * IND];         // transposed tf32 weights [n][k]
__device__ __align__(128) float    g_u[IND + 1];
__device__ __align__(128) float    g_scores[B_ * N_];
__device__ __align__(128) int      g_topk[B_ * TOPK];
__device__ __align__(128) float    g_Q[B_ * HID];
__device__ __align__(128) uint32_t g_x3u[B_ * NTOK * HID];  // tokens, tf32 (feeds K/V GEMM)
__device__ __align__(128) float    g_kk[B_ * NTOK * HID];
__device__ __align__(128) float    g_v [B_ * NTOK * HID];
__device__ __align__(128) float    g_q [B_ * HID];
__device__ __align__(128) float    g_logits[B_ * HEADS * NTOK];
__device__ __align__(128) float    g_stats[B_ * HEADS * 2];
__device__ __align__(128) float    g_O [B_ * HID];

// ---------------- helpers ----------------
__device__ __forceinline__ uint32_t f2tf(float x) {
    uint32_t r;
    asm("cvt.rna.tf32.f32 %0, %1;" : "=r"(r) : "f"(x));
    return r;
}
__device__ __forceinline__ uint32_t smem_u32(const void* p) {
    uint32_t a;
    asm("{ .reg .u64 t; cvta.to.shared.u64 t, %1; cvt.u32.u64 %0, t; }" : "=r"(a) : "l"(p));
    return a;
}
__device__ __forceinline__ void mma8(float* c, const uint32_t* a, const uint32_t* b) {
    asm volatile(
        "mma.sync.aligned.m16n8k8.row.col.f32.tf32.tf32.f32 "
        "{%0,%1,%2,%3}, {%4,%5,%6,%7}, {%8,%9}, {%0,%1,%2,%3};"
        : "+f"(c[0]), "+f"(c[1]), "+f"(c[2]), "+f"(c[3])
        : "r"(a[0]), "r"(a[1]), "r"(a[2]), "r"(a[3]), "r"(b[0]), "r"(b[1]));
}
__device__ __forceinline__ void cp16(uint32_t dst, const void* src, uint32_t sz) {
    asm volatile("cp.async.cg.shared.global [%0], [%1], 16, %2;"
                 :: "r"(dst), "l"(src), "r"(sz));
}
#define CP_COMMIT() asm volatile("cp.async.commit_group;")
#define CP_WAIT2()  asm volatile("cp.async.wait_group 2;")

// ---------------- GEMM tiling constants ----------------
#define BMT 128
#define BNT 128
#define BKT 32
#define ROWP 36                         /* padded row, floats */
#define ASZ  (BMT * ROWP * 4)           /* 18432 B */
#define STG  (2 * ASZ)                  /* A + B per stage   */
#define NSTAGE 4
#define GEMM_SMEM (NSTAGE * STG)        /* 147456 B */

// ---------------- elementwise fp32 -> tf32 ----------------
__global__ void cvt_tf32(const float4* __restrict__ in, uint4* __restrict__ out, int n4)
{
    const int i = blockIdx.x * blockDim.x + threadIdx.x;
    if (i >= n4) return;
    const float4 v = in[i];
    uint4 w;
    w.x = f2tf(v.x); w.y = f2tf(v.y); w.z = f2tf(v.z); w.w = f2tf(v.w);
    out[i] = w;
}

// ---------------- W[K][N] -> Wt[n][k] (tf32) ----------------
__global__ void transpose_tf32(const float* __restrict__ B, uint32_t* __restrict__ Bt,
                               int K, int N)
{
    __shared__ uint32_t t[32][33];
    const int k0 = blockIdx.x * 32, n0 = blockIdx.y * 32;
    const int x = threadIdx.x & 31, y = threadIdx.x >> 5;
#pragma unroll
    for (int i = 0; i < 32; i += 8)
        t[y + i][x] = f2tf(B[(size_t)(k0 + y + i) * N + n0 + x]);
    __syncthreads();
#pragma unroll
    for (int i = 0; i < 32; i += 8)
        Bt[(size_t)(n0 + y + i) * K + k0 + x] = t[x][y + i];
}

// ---------------- pipelined tf32 mma GEMM ----------------
// A[m][k] tf32, Bt[n][k] tf32. CTA 128x128, 8 warps (2m x 4n), warp 64x32.
// C cols < HID go to C1 (+bias1), cols >= HID go to C2 (+bias2)  [fused K|V].
__global__ void __launch_bounds__(256)
tc_gemm(const uint32_t* __restrict__ A, const uint32_t* __restrict__ Bt,
        const float* __restrict__ b1, const float* __restrict__ b2,
        float* __restrict__ C1, float* __restrict__ C2, int M, int K)
{
    extern __shared__ char smem[];
    const uint32_t sb = smem_u32(smem);
    const int tid  = threadIdx.x;
    const int warp = tid >> 5, lane = tid & 31;
    const int lr = lane >> 2, lc = lane & 3;
    const int bm = blockIdx.y * BMT, bn = blockIdx.x * BNT;
    const int wm = (warp >> 2) * 64, wn = (warp & 3) * 32;

    // stage loader: 8 x 16B chunks (4 A + 4 B) per thread
    auto load_stage = [&](int slot, int it) {
        const int k0 = it * BKT;
        const uint32_t base = sb + slot * STG;
#pragma unroll
        for (int i = 0; i < 4; i++) {
            const int g   = tid + i * 256;        // 0..1023
            const int row = g >> 3, off = g & 7;
            const int gr  = bm + row;
            cp16(base + row * (ROWP * 4) + off * 16,
                 A + (size_t)gr * K + k0 + off * 4, gr < M ? 16u : 0u);
        }
#pragma unroll
        for (int i = 0; i < 4; i++) {
            const int g   = tid + i * 256;
            const int row = g >> 3, off = g & 7;
            cp16(base + ASZ + row * (ROWP * 4) + off * 16,
                 Bt + (size_t)(bn + row) * K + k0 + off * 4, 16u);
        }
        CP_COMMIT();
    };

    float acc[4][4][4] = {};
    const int nIter = K / BKT;

#pragma unroll
    for (int s = 0; s < NSTAGE - 1; s++) load_stage(s, s);
    CP_WAIT2();
    __syncthreads();

    for (int it = 0; it < nIter; ++it) {
        const int nx = it + NSTAGE - 1;
        if (nx < nIter) load_stage(nx & (NSTAGE - 1), nx);

        const uint32_t* As = (const uint32_t*)(smem + (it & (NSTAGE - 1)) * STG);
        const uint32_t* Bs = As + ASZ / 4;

        uint32_t af[2][16], bf[2][8];
#pragma unroll
        for (int mi = 0; mi < 4; mi++) {
            const int r = wm + mi * 16 + lr;
            af[0][mi * 4 + 0] = As[r * ROWP + lc];
            af[0][mi * 4 + 1] = As[(r + 8) * ROWP + lc];
            af[0][mi * 4 + 2] = As[r * ROWP + lc + 4];
            af[0][mi * 4 + 3] = As[(r + 8) * ROWP + lc + 4];
        }
#pragma unroll
        for (int ni = 0; ni < 4; ni++) {
            const int n = wn + ni * 8 + lr;
            bf[0][ni * 2 + 0] = Bs[n * ROWP + lc];
            bf[0][ni * 2 + 1] = Bs[n * ROWP + lc + 4];
        }
#pragma unroll
        for (int ks = 0; ks < 4; ks++) {
            const int cur = ks & 1;
            if (ks < 3) {
                const int kb = (ks + 1) * 8;
                const int nxt = cur ^ 1;
#pragma unroll
                for (int mi = 0; mi < 4; mi++) {
                    const int r = wm + mi * 16 + lr;
                    af[nxt][mi * 4 + 0] = As[r * ROWP + kb + lc];
                    af[nxt][mi * 4 + 1] = As[(r + 8) * ROWP + kb + lc];
                    af[nxt][mi * 4 + 2] = As[r * ROWP + kb + lc + 4];
                    af[nxt][mi * 4 + 3] = As[(r + 8) * ROWP + kb + lc + 4];
                }
#pragma unroll
                for (int ni = 0; ni < 4; ni++) {
                    const int n = wn + ni * 8 + lr;
                    bf[nxt][ni * 2 + 0] = Bs[n * ROWP + kb + lc];
                    bf[nxt][ni * 2 + 1] = Bs[n * ROWP + kb + lc + 4];
                }
            }
#pragma unroll
            for (int mi = 0; mi < 4; mi++)
#pragma unroll
                for (int ni = 0; ni < 4; ni++)
                    mma8(acc[mi][ni], &af[cur][mi * 4], &bf[cur][ni * 2]);
        }
        CP_WAIT2();
        __syncthreads();
    }

    // epilogue
#pragma unroll
    for (int mi = 0; mi < 4; mi++) {
#pragma unroll
        for (int ni = 0; ni < 4; ni++) {
            const int r0 = bm + wm + mi * 16 + lr;
            const int cc = bn + wn + ni * 8 + lc * 2;
            const bool kv2 = cc >= HID;
            float* Co = kv2 ? C2 : C1;
            const float* bo = kv2 ? b2 : b1;
            const int c = kv2 ? cc - HID : cc;
            const float bx = bo[c], by = bo[c + 1];
            if (r0 < M) {
                Co[(size_t)r0 * HID + c]     = acc[mi][ni][0] + bx;
                Co[(size_t)r0 * HID + c + 1] = acc[mi][ni][1] + by;
            }
            if (r0 + 8 < M) {
                Co[(size_t)(r0 + 8) * HID + c]     = acc[mi][ni][2] + bx;
                Co[(size_t)(r0 + 8) * HID + c + 1] = acc[mi][ni][3] + by;
            }
        }
    }
}

// ---------------- fold: u = W_feat @ w_enc (fp32 exact path for gating) ----------
__global__ void fold_enc_k(const float* __restrict__ W_feat, const float* __restrict__ w_enc,
                           float* __restrict__ u)
{
    const int warp = (blockIdx.x * blockDim.x + threadIdx.x) >> 5;
    const int lane = threadIdx.x & 31;
    if (warp >= IND) return;
    const float* row = W_feat + (size_t)warp * HID;
    float s = 0.f;
    for (int k = lane; k < HID; k += 32) s = fmaf(row[k], w_enc[k], s);
#pragma unroll
    for (int o = 16; o; o >>= 1) s += __shfl_down_sync(0xffffffffu, s, o);
    if (lane == 0) u[warp] = s;
}
__global__ void fold_const_k(const float* __restrict__ b_feat, const float* __restrict__ w_enc,
                             const float* __restrict__ b_enc, float* __restrict__ u)
{
    __shared__ float red[512];
    red[threadIdx.x] = b_feat[threadIdx.x] * w_enc[threadIdx.x];
    __syncthreads();
    for (int t = 256; t; t >>= 1) {
        if (threadIdx.x < t) red[threadIdx.x] += red[threadIdx.x + t];
        __syncthreads();
    }
    if (threadIdx.x == 0) u[IND] = red[0] + b_enc[0];
}

// ---------------- gate logits from raw inputs (fp32, protects top-k) -------------
__global__ void scores_k(const float* __restrict__ inp, const float* __restrict__ u,
                         float* __restrict__ sc)
{
    const int warp = (blockIdx.x * blockDim.x + threadIdx.x) >> 5;
    const int lane = threadIdx.x & 31;
    if (warp >= B_ * N_) return;
    const float* row = inp + (size_t)warp * IND;
    float s = 0.f;
#pragma unroll 8
    for (int k = lane; k < IND; k += 32) s = fmaf(row[k], u[k], s);
#pragma unroll
    for (int o = 16; o; o >>= 1) s += __shfl_down_sync(0xffffffffu, s, o);
    if (lane == 0) sc[warp] = s + u[IND];
}

// ---------------- top-16: per-thread local top-16, then 16 argmax rounds ---------
__global__ void topk_k(const float* __restrict__ sc, int* __restrict__ tk)
{
    const int b = blockIdx.x;
    const float* s = sc + b * N_;
    __shared__ float cv[256 * 16];
    __shared__ int   ci[256 * 16];
    __shared__ float rv[256];
    __shared__ int   ri[256], rs[256];
    __shared__ int   sel[TOPK];

    float lv[16]; int li[16];
#pragma unroll
    for (int t = 0; t < 16; t++) { lv[t] = -FLT_MAX; li[t] = 0x7fffffff; }
    for (int i = threadIdx.x; i < N_; i += 256) {
        const float v = s[i];
        if (v > lv[15]) {
            int p = 15;
            for (int t = 14; t >= 0; t--)
                if (v > lv[t]) p = t; else break;
            for (int t = 15; t > p; t--) { lv[t] = lv[t - 1]; li[t] = li[t - 1]; }
            lv[p] = v; li[p] = i;
        }
    }
#pragma unroll
    for (int t = 0; t < 16; t++) { cv[threadIdx.x * 16 + t] = lv[t]; ci[threadIdx.x * 16 + t] = li[t]; }
    __syncthreads();

    for (int r = 0; r < TOPK; r++) {
        float bv = -FLT_MAX; int bi = 0x7fffffff, bs = 0;
#pragma unroll
        for (int t = 0; t < 16; t++) {
            const float v = cv[threadIdx.x * 16 + t];
            const int  ix = ci[threadIdx.x * 16 + t];
            if (v > bv || (v == bv && ix < bi)) { bv = v; bi = ix; bs = threadIdx.x * 16 + t; }
        }
        rv[threadIdx.x] = bv; ri[threadIdx.x] = bi; rs[threadIdx.x] = bs;
        __syncthreads();
        for (int t = 128; t; t >>= 1) {
            if (threadIdx.x < t) {
                if (rv[threadIdx.x + t] > rv[threadIdx.x] ||
                    (rv[threadIdx.x + t] == rv[threadIdx.x] && ri[threadIdx.x + t] < ri[threadIdx.x])) {
                    rv[threadIdx.x] = rv[threadIdx.x + t];
                    ri[threadIdx.x] = ri[threadIdx.x + t];
                    rs[threadIdx.x] = rs[threadIdx.x + t];
                }
            }
            __syncthreads();
        }
        if (threadIdx.x == 0) {
            sel[r] = ri[0];
            cv[rs[0]] = -FLT_MAX;
            ci[rs[0]] = 0x7fffffff;
        }
        __syncthreads();
    }
    if (threadIdx.x < TOPK) tk[b * TOPK + threadIdx.x] = sel[threadIdx.x];
}

// ---------------- Q = mean of top-k rows of (pre-relu) x -------------------------
__global__ void qmean_k(const float* __restrict__ x, const int* __restrict__ tk,
                        float* __restrict__ Q)
{
    const int b = blockIdx.x, c = threadIdx.x;
    float s = 0.f;
    for (int t = 0; t < TOPK; t++) {
        const int idx = tk[b * TOPK + t];
        s += x[((size_t)(b * N_ + idx)) * HID + c];
    }
    Q[b * HID + c] = s * (1.f / TOPK);
}

// ---------------- fused relu + depthwise 3x3 conv + bias + residual (-> tf32) ----
__global__ void conv_k(const float* __restrict__ x, const float* __restrict__ Q,
                       const float* __restrict__ cw, const float* __restrict__ cb,
                       uint32_t* __restrict__ x3)
{
    const int i = blockIdx.x * blockDim.x + threadIdx.x;
    if (i >= B_ * NPAD * HID) return;
    const int c = i & (HID - 1);
    const int n = (i >> 9) % NPAD;
    const int b = i / (NPAD * HID);
    const int pi = n / HH, pj = n % HH;
    const float* xb = x + (size_t)b * N_ * HID;
    const float qc = Q[b * HID + c];
    float acc = 0.f, center = 0.f;
#pragma unroll
    for (int di = 0; di < 3; di++) {
        const int ii = pi + di - 1;
        if (ii < 0 || ii >= HH) continue;
#pragma unroll
        for (int dj = 0; dj < 3; dj++) {
            const int jj = pj + dj - 1;
            if (jj < 0 || jj >= HH) continue;
            int m = ii * HH + jj;
            if (m >= N_) m -= N_;
            const float vv = fmaxf(xb[(size_t)m * HID + c] - qc, 0.f);
            acc = fmaf(vv, cw[c * 9 + di * 3 + dj], acc);
            if (di == 1 && dj == 1) center = vv;
        }
    }
    x3[((size_t)b * NTOK + n + 1) * HID + c] = f2tf(acc + cb[c] + center);
}

// ---------------- cls token -> x3 row 0 (tf32) -----------------------------------
__global__ void cls_k(const float* __restrict__ cls, uint32_t* __restrict__ x3)
{
    x3[((size_t)blockIdx.x * NTOK) * HID + threadIdx.x] = f2tf(cls[threadIdx.x]);
}

// ---------------- tiny row GEMM: Y[b,:] = X[b,:] @ W (HIDxHID) + bias ------------
__global__ void rowmat_k(const float* __restrict__ X, const float* __restrict__ W,
                         const float* __restrict__ bias, float* __restrict__ Y)
{
    const int b = blockIdx.x, c = threadIdx.x;
    __shared__ float xr[HID];
    xr[c] = X[b * HID + c];
    __syncthreads();
    float s = bias[c];
    for (int k = 0; k < HID; k++) s = fmaf(xr[k], W[k * HID + c], s);
    Y[b * HID + c] = s;
}

// ---------------- attention logits: q . k / sqrt(HID) ----------------------------
__global__ void logits_k(const float* __restrict__ q, const float* __restrict__ kk,
                         float* __restrict__ logits)
{
    const int bh = blockIdx.x;
    const int b = bh >> 3, h = bh & 7;
    __shared__ float qs[DH];
    if (threadIdx.x < DH) qs[threadIdx.x] = q[b * HID + h * DH + threadIdx.x];
    __syncthreads();
    const int k = blockIdx.y * blockDim.x + threadIdx.x;
    if (k >= NTOK) return;
    const float* kp = kk + ((size_t)(b * NTOK + k)) * HID + h * DH;
    float s = 0.f;
#pragma unroll
    for (int d2 = 0; d2 < DH; d2 += 4) {
        const float4 kv = *(const float4*)(kp + d2);
        s = fmaf(qs[d2 + 0], kv.x, s);
        s = fmaf(qs[d2 + 1], kv.y, s);
        s = fmaf(qs[d2 + 2], kv.z, s);
        s = fmaf(qs[d2 + 3], kv.w, s);
    }
    logits[bh * NTOK + k] = s * 0.04419417382415922f;  // 1/sqrt(512)
}

// ---------------- softmax stats (max, sumexp) per (b,h) --------------------------
__global__ void stats_k(const float* __restrict__ logits, float* __restrict__ stats)
{
    const int bh = blockIdx.x;
    const float* lg = logits + bh * NTOK;
    __shared__ float red[256];
    float mx = -FLT_MAX;
    for (int k = threadIdx.x; k < NTOK; k += 256) mx = fmaxf(mx, lg[k]);
    red[threadIdx.x] = mx; __syncthreads();
    for (int s = 128; s; s >>= 1) {
        if (threadIdx.x < s) red[threadIdx.x] = fmaxf(red[threadIdx.x], red[threadIdx.x + s]);
        __syncthreads();
    }
    mx = red[0]; __syncthreads();
    float sm = 0.f;
    for (int k = threadIdx.x; k < NTOK; k += 256) sm += expf(lg[k] - mx);
    red[threadIdx.x] = sm; __syncthreads();
    for (int s = 128; s; s >>= 1) {
        if (threadIdx.x < s) red[threadIdx.x] += red[threadIdx.x + s];
        __syncthreads();
    }
    if (threadIdx.x == 0) { stats[bh * 2] = mx; stats[bh * 2 + 1] = red[0]; }
}

// ---------------- O = q + softmax(logits) @ v ------------------------------------
__global__ void attno_k(const float* __restrict__ logits, const float* __restrict__ stats,
                        const float* __restrict__ v, const float* __restrict__ q,
                        float* __restrict__ O)
{
    const int bh = blockIdx.x;
    const int b = bh >> 3, h = bh & 7;
    const float mx = stats[bh * 2];
    const float inv_den = 1.f / stats[bh * 2 + 1];
    const int d  = threadIdx.x & 63;
    const int kg = threadIdx.x >> 6;
    float acc = 0.f;
    for (int k = kg; k < NTOK; k += 4) {
        const float w = expf(logits[bh * NTOK + k] - mx);
        acc = fmaf(w, v[((size_t)(b * NTOK + k)) * HID + h * DH + d], acc);
    }
    __shared__ float red[256];
    red[threadIdx.x] = acc; __syncthreads();
    if (kg == 0) {
        acc = red[d] + red[64 + d] + red[128 + d] + red[192 + d];
        O[b * HID + h * DH + d] = q[b * HID + h * DH + d] + acc * inv_den;
    }
}

// ---------------- O += relu(O @ Wo + bo) -----------------------------------------
__global__ void otrans_k(const float* __restrict__ Wo, const float* __restrict__ bo,
                         float* __restrict__ O)
{
    const int b = blockIdx.x, c = threadIdx.x;
    __shared__ float orow[HID];
    orow[c] = O[b * HID + c];
    __syncthreads();
    float s = bo[c];
    for (int k = 0; k < HID; k++) s = fmaf(orow[k], Wo[k * HID + c], s);
    O[b * HID + c] = orow[c] + fmaxf(s, 0.f);
}

// ---------------- out = O @ Wc + bc ----------------------------------------------
__global__ void final_k(const float* __restrict__ O, const float* __restrict__ Wc,
                        const float* __restrict__ bc, float* __restrict__ out)
{
    const int b = blockIdx.x >> 1, j = blockIdx.x & 1;
    __shared__ float red[128];
    float s = 0.f;
    for (int c = threadIdx.x; c < HID; c += 128) s = fmaf(O[b * HID + c], Wc[c * NCLS + j], s);
    red[threadIdx.x] = s; __syncthreads();
    for (int t = 64; t; t >>= 1) {
        if (threadIdx.x < t) red[threadIdx.x] += red[threadIdx.x + t];
        __syncthreads();
    }
    if (threadIdx.x == 0) out[b * NCLS + j] = red[0] + bc[j];
}

// =================================================================================
extern "C" void kernel_launch(void* const* d_in, const int* in_sizes, int n_in,
                              void* d_out, int out_size)
{
    const float* inputs = (const float*)d_in[0];
    const float* W_feat = (const float*)d_in[1];
    const float* b_feat = (const float*)d_in[2];
    const float* w_enc  = (const float*)d_in[3];
    const float* b_enc  = (const float*)d_in[4];
    const float* cls    = (const float*)d_in[5];
    const float* conv_w = (const float*)d_in[6];
    const float* conv_b = (const float*)d_in[7];
    const float* Wq     = (const float*)d_in[8];
    const float* bq     = (const float*)d_in[9];
    const float* Wk     = (const float*)d_in[10];
    const float* bk     = (const float*)d_in[11];
    const float* Wv     = (const float*)d_in[12];
    const float* bv     = (const float*)d_in[13];
    const float* Wo     = (const float*)d_in[14];
    const float* bo     = (const float*)d_in[15];
    const float* Wc     = (const float*)d_in[16];
    const float* bc     = (const float*)d_in[17];
    float* out = (float*)d_out;
    (void)in_sizes; (void)n_in; (void)out_size;

    float *x, *u, *scores, *Q, *kk, *v, *q, *logits, *stats, *O;
    uint32_t *At, *Bt, *x3u;
    int* topk;
    cudaGetSymbolAddress((void**)&x,      g_x);
    cudaGetSymbolAddress((void**)&At,     g_At);
    cudaGetSymbolAddress((void**)&Bt,     g_Bt);
    cudaGetSymbolAddress((void**)&u,      g_u);
    cudaGetSymbolAddress((void**)&scores, g_scores);
    cudaGetSymbolAddress((void**)&topk,   g_topk);
    cudaGetSymbolAddress((void**)&Q,      g_Q);
    cudaGetSymbolAddress((void**)&x3u,    g_x3u);
    cudaGetSymbolAddress((void**)&kk,     g_kk);
    cudaGetSymbolAddress((void**)&v,      g_v);
    cudaGetSymbolAddress((void**)&q,      g_q);
    cudaGetSymbolAddress((void**)&logits, g_logits);
    cudaGetSymbolAddress((void**)&stats,  g_stats);
    cudaGetSymbolAddress((void**)&O,      g_O);

    cudaFuncSetAttribute(tc_gemm, cudaFuncAttributeMaxDynamicSharedMemorySize, GEMM_SMEM);

    // 0. fold enc weights (fp32-exact gating path)
    fold_enc_k<<<IND / 8, 256>>>(W_feat, w_enc, u);
    fold_const_k<<<1, 512>>>(b_feat, w_enc, b_enc, u);
    // 1. pre-convert operands; x = inputs @ W_feat + b_feat  (mma.sync tf32)
    cvt_tf32<<<(B_ * N_ * IND / 4 + 255) / 256, 256>>>(
        (const float4*)inputs, (uint4*)At, B_ * N_ * IND / 4);
    transpose_tf32<<<dim3(IND / 32, HID / 32), 256>>>(W_feat, Bt, IND, HID);
    tc_gemm<<<dim3(HID / BNT, B_ * N_ / BMT), 256, GEMM_SMEM>>>(
        At, Bt, b_feat, b_feat, x, x, B_ * N_, IND);
    // 2. gate logits from raw inputs (fp32 exact)
    scores_k<<<(B_ * N_) / 8, 256>>>(inputs, u, scores);
    // 3. top-16 per batch
    topk_k<<<B_, 256>>>(scores, topk);
    // 4. Q = mean of selected (pre-relu) rows
    qmean_k<<<B_, HID>>>(x, topk, Q);
    // 5+6. fused relu + depthwise conv + residual -> x3 (tf32)
    conv_k<<<(B_ * NPAD * HID + 255) / 256, 256>>>(x, Q, conv_w, conv_b, x3u);
    // 7. cls token -> x3 row 0
    cls_k<<<B_, HID>>>(cls, x3u);
    // 8. fused K|V projection: Bt = [Wk^T | Wv^T], one GEMM with N=1024
    transpose_tf32<<<dim3(HID / 32, HID / 32), 256>>>(Wk, Bt, HID, HID);
    transpose_tf32<<<dim3(HID / 32, HID / 32), 256>>>(Wv, Bt + HID * HID, HID, HID);
    tc_gemm<<<dim3(2 * HID / BNT, (B_ * NTOK + BMT - 1) / BMT), 256, GEMM_SMEM>>>(
        x3u, Bt, bk, bv, kk, v, B_ * NTOK, HID);
    // 10. q = Q @ Wq + bq
    rowmat_k<<<B_, HID>>>(Q, Wq, bq, q);
    // 11. attention logits
    logits_k<<<dim3(B_ * HEADS, (NTOK + 255) / 256), 256>>>(q, kk, logits);
    // 12. softmax stats
    stats_k<<<B_ * HEADS, 256>>>(logits, stats);
    // 13. O = q + A @ v
    attno_k<<<B_ * HEADS, 256>>>(logits, stats, v, q, O);
    // 14. O += relu(O @ Wo + bo)
    otrans_k<<<B_, HID>>>(Wo, bo, O);
    // 15. out = O @ Wc + bc
    final_k<<<B_ * NCLS, 128>>>(O, Wc, bc, out);
}

// round 6
// speedup vs baseline: 1.9078x; 1.1662x over previous
#include <cuda_runtime.h>
#include <cuda_fp16.h>
#include <math.h>
#include <float.h>
#include <stdint.h>

#define B_    4
#define N_    8192
#define IND   1024
#define HID   512
#define HEADS 8
#define TOPK  16
#define NCLS  2
#define HH    91
#define NPAD  8281   /* HH*HH */
#define NTOK  8282   /* NPAD + 1 cls */
#define DH    64     /* HID/HEADS */

// ---------------- scratch (no allocations allowed) ----------------
__device__ __align__(128) float  g_x[B_ * N_ * HID];       // GEMM1 out (fp32)
__device__ __align__(128) __half g_Ah[B_ * N_ * IND];      // inputs in fp16
__device__ __align__(128) __half g_Bh[IND * HID];          // transposed fp16 weights [n][k]
__device__ __align__(128) float  g_u[IND + 1];
__device__ __align__(128) float  g_scores[B_ * N_];
__device__ __align__(128) int    g_topk[B_ * TOPK];
__device__ __align__(128) float  g_Q[B_ * HID];
__device__ __align__(128) __half g_x3h[B_ * NTOK * HID];   // tokens fp16 (feeds K/V GEMM)
__device__ __align__(128) float  g_kk[B_ * NTOK * HID];
__device__ __align__(128) float  g_v [B_ * NTOK * HID];
__device__ __align__(128) float  g_q [B_ * HID];
__device__ __align__(128) float  g_logits[B_ * HEADS * NTOK];
__device__ __align__(128) float  g_stats[B_ * HEADS * 2];
__device__ __align__(128) float  g_O [B_ * HID];

// ---------------- helpers ----------------
__device__ __forceinline__ uint32_t smem_u32(const void* p) {
    uint32_t a;
    asm("{ .reg .u64 t; cvta.to.shared.u64 t, %1; cvt.u32.u64 %0, t; }" : "=r"(a) : "l"(p));
    return a;
}
__device__ __forceinline__ void mma16(float* c, const uint32_t* a, const uint32_t* b) {
    asm volatile(
        "mma.sync.aligned.m16n8k16.row.col.f32.f16.f16.f32 "
        "{%0,%1,%2,%3}, {%4,%5,%6,%7}, {%8,%9}, {%0,%1,%2,%3};"
        : "+f"(c[0]), "+f"(c[1]), "+f"(c[2]), "+f"(c[3])
        : "r"(a[0]), "r"(a[1]), "r"(a[2]), "r"(a[3]), "r"(b[0]), "r"(b[1]));
}
__device__ __forceinline__ void ldsm4(uint32_t* r, uint32_t a) {
    asm volatile("ldmatrix.sync.aligned.m8n8.x4.shared.b16 {%0,%1,%2,%3}, [%4];"
                 : "=r"(r[0]), "=r"(r[1]), "=r"(r[2]), "=r"(r[3]) : "r"(a));
}
__device__ __forceinline__ void cp16(uint32_t dst, const void* src, uint32_t sz) {
    asm volatile("cp.async.cg.shared.global [%0], [%1], 16, %2;"
                 :: "r"(dst), "l"(src), "r"(sz));
}
#define CP_COMMIT() asm volatile("cp.async.commit_group;")
#define CP_WAIT2()  asm volatile("cp.async.wait_group 2;")

// ---------------- GEMM tiling ----------------
// CTA 128x128, BK=32 (fp16). Padded row = 40 halves = 80 B: 8 rows at 80B
// stride touch all 32 banks exactly once -> conflict-free ldmatrix.
#define BMT 128
#define BNT 128
#define BKT 32
#define ROWB 80
#define TILEB (128 * ROWB)      /* 10240 B */
#define STG   (2 * TILEB)       /* 20480 B */
#define NSTAGE 4
#define GEMM_SMEM (NSTAGE * STG) /* 81920 B */

// ---------------- fp32 -> fp16 bulk convert (8 elems/thread) ----------------
__global__ void cvt_f16(const float4* __restrict__ in, uint4* __restrict__ out, int n8)
{
    const int i = blockIdx.x * blockDim.x + threadIdx.x;
    if (i >= n8) return;
    const float4 a = in[2 * i], b = in[2 * i + 1];
    union { uint4 u; __half2 h[4]; } w;
    w.h[0] = __floats2half2_rn(a.x, a.y);
    w.h[1] = __floats2half2_rn(a.z, a.w);
    w.h[2] = __floats2half2_rn(b.x, b.y);
    w.h[3] = __floats2half2_rn(b.z, b.w);
    out[i] = w.u;
}

// ---------------- W[K][N] fp32 -> Wt[n][k] fp16 ----------------
__global__ void transpose_f16(const float* __restrict__ B, __half* __restrict__ Bt,
                              int K, int N)
{
    __shared__ __half t[32][33];
    const int k0 = blockIdx.x * 32, n0 = blockIdx.y * 32;
    const int x = threadIdx.x & 31, y = threadIdx.x >> 5;
#pragma unroll
    for (int i = 0; i < 32; i += 8)
        t[y + i][x] = __float2half_rn(B[(size_t)(k0 + y + i) * N + n0 + x]);
    __syncthreads();
#pragma unroll
    for (int i = 0; i < 32; i += 8)
        Bt[(size_t)(n0 + y + i) * K + k0 + x] = t[x][y + i];
}

// ---------------- pipelined fp16 mma GEMM ----------------
// A[m][k] fp16, Bt[n][k] fp16. CTA 128x128, 8 warps (2m x 4n), warp 64x32.
// C cols < HID -> C1 (+b1); cols >= HID -> C2 (+b2)  [fused K|V].
__global__ void __launch_bounds__(256)
tc_gemm(const __half* __restrict__ A, const __half* __restrict__ Bt,
        const float* __restrict__ b1, const float* __restrict__ b2,
        float* __restrict__ C1, float* __restrict__ C2, int M, int K)
{
    extern __shared__ char smem[];
    const uint32_t sb = smem_u32(smem);
    const int tid  = threadIdx.x;
    const int warp = tid >> 5, lane = tid & 31;
    const int lr = lane >> 2, lc = lane & 3;
    const int bm = blockIdx.y * BMT, bn = blockIdx.x * BNT;
    const int wm = (warp >> 2) * 64, wn = (warp & 3) * 32;

    // ldmatrix source lane mappings
    const int a_row = lane & 15, a_kh = lane >> 4;                // A: 16 rows x (k lo|hi)
    const int b_row = (lane & 7) + ((lane >> 4) << 3);            // B: n lo8|hi8
    const int b_kh  = (lane >> 3) & 1;

    auto load_stage = [&](int slot, int it) {
        const int k0 = it * BKT;
        const uint32_t base = sb + slot * STG;
#pragma unroll
        for (int i = 0; i < 2; i++) {
            const int g = tid + i * 256;          // 0..511
            const int row = g >> 2, off = g & 3;
            const int gr = bm + row;
            cp16(base + row * ROWB + off * 16,
                 A + (size_t)gr * K + k0 + off * 8, gr < M ? 16u : 0u);
        }
#pragma unroll
        for (int i = 0; i < 2; i++) {
            const int g = tid + i * 256;
            const int row = g >> 2, off = g & 3;
            cp16(base + TILEB + row * ROWB + off * 16,
                 Bt + (size_t)(bn + row) * K + k0 + off * 8, 16u);
        }
        CP_COMMIT();
    };

    float acc[4][4][4] = {};
    const int nIter = K / BKT;

#pragma unroll
    for (int s = 0; s < NSTAGE - 1; s++) load_stage(s, s);
    CP_WAIT2();
    __syncthreads();

    for (int it = 0; it < nIter; ++it) {
        const int nx = it + NSTAGE - 1;
        if (nx < nIter) load_stage(nx & (NSTAGE - 1), nx);

        const uint32_t Asb = sb + (it & (NSTAGE - 1)) * STG;
        const uint32_t Bsb = Asb + TILEB;

#pragma unroll
        for (int k16 = 0; k16 < 2; k16++) {
            uint32_t af[4][4], bf[2][4];
#pragma unroll
            for (int mi = 0; mi < 4; mi++)
                ldsm4(af[mi], Asb + (wm + mi * 16 + a_row) * ROWB + k16 * 32 + a_kh * 16);
#pragma unroll
            for (int nj = 0; nj < 2; nj++)
                ldsm4(bf[nj], Bsb + (wn + nj * 16 + b_row) * ROWB + k16 * 32 + b_kh * 16);
#pragma unroll
            for (int mi = 0; mi < 4; mi++)
#pragma unroll
                for (int ni = 0; ni < 4; ni++)
                    mma16(acc[mi][ni], af[mi], &bf[ni >> 1][(ni & 1) * 2]);
        }
        CP_WAIT2();
        __syncthreads();
    }

    // epilogue
#pragma unroll
    for (int mi = 0; mi < 4; mi++) {
#pragma unroll
        for (int ni = 0; ni < 4; ni++) {
            const int r0 = bm + wm + mi * 16 + lr;
            const int cc = bn + wn + ni * 8 + lc * 2;
            const bool kv2 = cc >= HID;
            float* Co = kv2 ? C2 : C1;
            const float* bo = kv2 ? b2 : b1;
            const int c = kv2 ? cc - HID : cc;
            const float bx = bo[c], by = bo[c + 1];
            if (r0 < M) {
                Co[(size_t)r0 * HID + c]     = acc[mi][ni][0] + bx;
                Co[(size_t)r0 * HID + c + 1] = acc[mi][ni][1] + by;
            }
            if (r0 + 8 < M) {
                Co[(size_t)(r0 + 8) * HID + c]     = acc[mi][ni][2] + bx;
                Co[(size_t)(r0 + 8) * HID + c + 1] = acc[mi][ni][3] + by;
            }
        }
    }
}

// ---------------- fold: u = W_feat @ w_enc (fp32 exact path for gating) ----------
__global__ void fold_enc_k(const float* __restrict__ W_feat, const float* __restrict__ w_enc,
                           float* __restrict__ u)
{
    const int warp = (blockIdx.x * blockDim.x + threadIdx.x) >> 5;
    const int lane = threadIdx.x & 31;
    if (warp >= IND) return;
    const float* row = W_feat + (size_t)warp * HID;
    float s = 0.f;
    for (int k = lane; k < HID; k += 32) s = fmaf(row[k], w_enc[k], s);
#pragma unroll
    for (int o = 16; o; o >>= 1) s += __shfl_down_sync(0xffffffffu, s, o);
    if (lane == 0) u[warp] = s;
}
__global__ void fold_const_k(const float* __restrict__ b_feat, const float* __restrict__ w_enc,
                             const float* __restrict__ b_enc, float* __restrict__ u)
{
    __shared__ float red[512];
    red[threadIdx.x] = b_feat[threadIdx.x] * w_enc[threadIdx.x];
    __syncthreads();
    for (int t = 256; t; t >>= 1) {
        if (threadIdx.x < t) red[threadIdx.x] += red[threadIdx.x + t];
        __syncthreads();
    }
    if (threadIdx.x == 0) u[IND] = red[0] + b_enc[0];
}

// ---------------- gate logits from raw inputs (fp32, protects top-k) -------------
__global__ void scores_k(const float* __restrict__ inp, const float* __restrict__ u,
                         float* __restrict__ sc)
{
    const int warp = (blockIdx.x * blockDim.x + threadIdx.x) >> 5;
    const int lane = threadIdx.x & 31;
    if (warp >= B_ * N_) return;
    const float* row = inp + (size_t)warp * IND;
    float s = 0.f;
#pragma unroll 8
    for (int k = lane; k < IND; k += 32) s = fmaf(row[k], u[k], s);
#pragma unroll
    for (int o = 16; o; o >>= 1) s += __shfl_down_sync(0xffffffffu, s, o);
    if (lane == 0) sc[warp] = s + u[IND];
}

// ---------------- top-16: per-thread local top-16, then 16 argmax rounds ---------
__global__ void topk_k(const float* __restrict__ sc, int* __restrict__ tk)
{
    const int b = blockIdx.x;
    const float* s = sc + b * N_;
    __shared__ float cv[256 * 16];
    __shared__ int   ci[256 * 16];
    __shared__ float rv[256];
    __shared__ int   ri[256], rs[256];
    __shared__ int   sel[TOPK];

    float lv[16]; int li[16];
#pragma unroll
    for (int t = 0; t < 16; t++) { lv[t] = -FLT_MAX; li[t] = 0x7fffffff; }
    for (int i = threadIdx.x; i < N_; i += 256) {
        const float v = s[i];
        if (v > lv[15]) {
            int p = 15;
            for (int t = 14; t >= 0; t--)
                if (v > lv[t]) p = t; else break;
            for (int t = 15; t > p; t--) { lv[t] = lv[t - 1]; li[t] = li[t - 1]; }
            lv[p] = v; li[p] = i;
        }
    }
#pragma unroll
    for (int t = 0; t < 16; t++) { cv[threadIdx.x * 16 + t] = lv[t]; ci[threadIdx.x * 16 + t] = li[t]; }
    __syncthreads();

    for (int r = 0; r < TOPK; r++) {
        float bv = -FLT_MAX; int bi = 0x7fffffff, bs = 0;
#pragma unroll
        for (int t = 0; t < 16; t++) {
            const float v = cv[threadIdx.x * 16 + t];
            const int  ix = ci[threadIdx.x * 16 + t];
            if (v > bv || (v == bv && ix < bi)) { bv = v; bi = ix; bs = threadIdx.x * 16 + t; }
        }
        rv[threadIdx.x] = bv; ri[threadIdx.x] = bi; rs[threadIdx.x] = bs;
        __syncthreads();
        for (int t = 128; t; t >>= 1) {
            if (threadIdx.x < t) {
                if (rv[threadIdx.x + t] > rv[threadIdx.x] ||
                    (rv[threadIdx.x + t] == rv[threadIdx.x] && ri[threadIdx.x + t] < ri[threadIdx.x])) {
                    rv[threadIdx.x] = rv[threadIdx.x + t];
                    ri[threadIdx.x] = ri[threadIdx.x + t];
                    rs[threadIdx.x] = rs[threadIdx.x + t];
                }
            }
            __syncthreads();
        }
        if (threadIdx.x == 0) {
            sel[r] = ri[0];
            cv[rs[0]] = -FLT_MAX;
            ci[rs[0]] = 0x7fffffff;
        }
        __syncthreads();
    }
    if (threadIdx.x < TOPK) tk[b * TOPK + threadIdx.x] = sel[threadIdx.x];
}

// ---------------- Q = mean of top-k rows of (pre-relu) x -------------------------
__global__ void qmean_k(const float* __restrict__ x, const int* __restrict__ tk,
                        float* __restrict__ Q)
{
    const int b = blockIdx.x, c = threadIdx.x;
    float s = 0.f;
    for (int t = 0; t < TOPK; t++) {
        const int idx = tk[b * TOPK + t];
        s += x[((size_t)(b * N_ + idx)) * HID + c];
    }
    Q[b * HID + c] = s * (1.f / TOPK);
}

// ---------------- fused relu + depthwise 3x3 conv + bias + residual (-> fp16) ----
__global__ void conv_k(const float* __restrict__ x, const float* __restrict__ Q,
                       const float* __restrict__ cw, const float* __restrict__ cb,
                       __half* __restrict__ x3)
{
    const int i = blockIdx.x * blockDim.x + threadIdx.x;
    if (i >= B_ * NPAD * HID) return;
    const int c = i & (HID - 1);
    const int n = (i >> 9) % NPAD;
    const int b = i / (NPAD * HID);
    const int pi = n / HH, pj = n % HH;
    const float* xb = x + (size_t)b * N_ * HID;
    const float qc = Q[b * HID + c];
    float acc = 0.f, center = 0.f;
#pragma unroll
    for (int di = 0; di < 3; di++) {
        const int ii = pi + di - 1;
        if (ii < 0 || ii >= HH) continue;
#pragma unroll
        for (int dj = 0; dj < 3; dj++) {
            const int jj = pj + dj - 1;
            if (jj < 0 || jj >= HH) continue;
            int m = ii * HH + jj;
            if (m >= N_) m -= N_;
            const float vv = fmaxf(xb[(size_t)m * HID + c] - qc, 0.f);
            acc = fmaf(vv, cw[c * 9 + di * 3 + dj], acc);
            if (di == 1 && dj == 1) center = vv;
        }
    }
    x3[((size_t)b * NTOK + n + 1) * HID + c] = __float2half_rn(acc + cb[c] + center);
}

// ---------------- cls token -> x3 row 0 (fp16) -----------------------------------
__global__ void cls_k(const float* __restrict__ cls, __half* __restrict__ x3)
{
    x3[((size_t)blockIdx.x * NTOK) * HID + threadIdx.x] = __float2half_rn(cls[threadIdx.x]);
}

// ---------------- tiny row GEMM: Y[b,:] = X[b,:] @ W (HIDxHID) + bias ------------
__global__ void rowmat_k(const float* __restrict__ X, const float* __restrict__ W,
                         const float* __restrict__ bias, float* __restrict__ Y)
{
    const int b = blockIdx.x, c = threadIdx.x;
    __shared__ float xr[HID];
    xr[c] = X[b * HID + c];
    __syncthreads();
    float s = bias[c];
    for (int k = 0; k < HID; k++) s = fmaf(xr[k], W[k * HID + c], s);
    Y[b * HID + c] = s;
}

// ---------------- attention logits: q . k / sqrt(HID) ----------------------------
__global__ void logits_k(const float* __restrict__ q, const float* __restrict__ kk,
                         float* __restrict__ logits)
{
    const int bh = blockIdx.x;
    const int b = bh >> 3, h = bh & 7;
    __shared__ float qs[DH];
    if (threadIdx.x < DH) qs[threadIdx.x] = q[b * HID + h * DH + threadIdx.x];
    __syncthreads();
    const int k = blockIdx.y * blockDim.x + threadIdx.x;
    if (k >= NTOK) return;
    const float* kp = kk + ((size_t)(b * NTOK + k)) * HID + h * DH;
    float s = 0.f;
#pragma unroll
    for (int d2 = 0; d2 < DH; d2 += 4) {
        const float4 kv = *(const float4*)(kp + d2);
        s = fmaf(qs[d2 + 0], kv.x, s);
        s = fmaf(qs[d2 + 1], kv.y, s);
        s = fmaf(qs[d2 + 2], kv.z, s);
        s = fmaf(qs[d2 + 3], kv.w, s);
    }
    logits[bh * NTOK + k] = s * 0.04419417382415922f;  // 1/sqrt(512)
}

// ---------------- softmax stats (max, sumexp) per (b,h) --------------------------
__global__ void stats_k(const float* __restrict__ logits, float* __restrict__ stats)
{
    const int bh = blockIdx.x;
    const float* lg = logits + bh * NTOK;
    __shared__ float red[256];
    float mx = -FLT_MAX;
    for (int k = threadIdx.x; k < NTOK; k += 256) mx = fmaxf(mx, lg[k]);
    red[threadIdx.x] = mx; __syncthreads();
    for (int s = 128; s; s >>= 1) {
        if (threadIdx.x < s) red[threadIdx.x] = fmaxf(red[threadIdx.x], red[threadIdx.x + s]);
        __syncthreads();
    }
    mx = red[0]; __syncthreads();
    float sm = 0.f;
    for (int k = threadIdx.x; k < NTOK; k += 256) sm += expf(lg[k] - mx);
    red[threadIdx.x] = sm; __syncthreads();
    for (int s = 128; s; s >>= 1) {
        if (threadIdx.x < s) red[threadIdx.x] += red[threadIdx.x + s];
        __syncthreads();
    }
    if (threadIdx.x == 0) { stats[bh * 2] = mx; stats[bh * 2 + 1] = red[0]; }
}

// ---------------- O = q + softmax(logits) @ v ------------------------------------
__global__ void attno_k(const float* __restrict__ logits, const float* __restrict__ stats,
                        const float* __restrict__ v, const float* __restrict__ q,
                        float* __restrict__ O)
{
    const int bh = blockIdx.x;
    const int b = bh >> 3, h = bh & 7;
    const float mx = stats[bh * 2];
    const float inv_den = 1.f / stats[bh * 2 + 1];
    const int d  = threadIdx.x & 63;
    const int kg = threadIdx.x >> 6;
    float acc = 0.f;
    for (int k = kg; k < NTOK; k += 4) {
        const float w = expf(logits[bh * NTOK + k] - mx);
        acc = fmaf(w, v[((size_t)(b * NTOK + k)) * HID + h * DH + d], acc);
    }
    __shared__ float red[256];
    red[threadIdx.x] = acc; __syncthreads();
    if (kg == 0) {
        acc = red[d] + red[64 + d] + red[128 + d] + red[192 + d];
        O[b * HID + h * DH + d] = q[b * HID + h * DH + d] + acc * inv_den;
    }
}

// ---------------- O += relu(O @ Wo + bo) -----------------------------------------
__global__ void otrans_k(const float* __restrict__ Wo, const float* __restrict__ bo,
                         float* __restrict__ O)
{
    const int b = blockIdx.x, c = threadIdx.x;
    __shared__ float orow[HID];
    orow[c] = O[b * HID + c];
    __syncthreads();
    float s = bo[c];
    for (int k = 0; k < HID; k++) s = fmaf(orow[k], Wo[k * HID + c], s);
    O[b * HID + c] = orow[c] + fmaxf(s, 0.f);
}

// ---------------- out = O @ Wc + bc ----------------------------------------------
__global__ void final_k(const float* __restrict__ O, const float* __restrict__ Wc,
                        const float* __restrict__ bc, float* __restrict__ out)
{
    const int b = blockIdx.x >> 1, j = blockIdx.x & 1;
    __shared__ float red[128];
    float s = 0.f;
    for (int c = threadIdx.x; c < HID; c += 128) s = fmaf(O[b * HID + c], Wc[c * NCLS + j], s);
    red[threadIdx.x] = s; __syncthreads();
    for (int t = 64; t; t >>= 1) {
        if (threadIdx.x < t) red[threadIdx.x] += red[threadIdx.x + t];
        __syncthreads();
    }
    if (threadIdx.x == 0) out[b * NCLS + j] = red[0] + bc[j];
}

// =================================================================================
extern "C" void kernel_launch(void* const* d_in, const int* in_sizes, int n_in,
                              void* d_out, int out_size)
{
    const float* inputs = (const float*)d_in[0];
    const float* W_feat = (const float*)d_in[1];
    const float* b_feat = (const float*)d_in[2];
    const float* w_enc  = (const float*)d_in[3];
    const float* b_enc  = (const float*)d_in[4];
    const float* cls    = (const float*)d_in[5];
    const float* conv_w = (const float*)d_in[6];
    const float* conv_b = (const float*)d_in[7];
    const float* Wq     = (const float*)d_in[8];
    const float* bq     = (const float*)d_in[9];
    const float* Wk     = (const float*)d_in[10];
    const float* bk     = (const float*)d_in[11];
    const float* Wv     = (const float*)d_in[12];
    const float* bv     = (const float*)d_in[13];
    const float* Wo     = (const float*)d_in[14];
    const float* bo     = (const float*)d_in[15];
    const float* Wc     = (const float*)d_in[16];
    const float* bc     = (const float*)d_in[17];
    float* out = (float*)d_out;
    (void)in_sizes; (void)n_in; (void)out_size;

    float *x, *u, *scores, *Q, *kk, *v, *q, *logits, *stats, *O;
    __half *Ah, *Bh, *x3h;
    int* topk;
    cudaGetSymbolAddress((void**)&x,      g_x);
    cudaGetSymbolAddress((void**)&Ah,     g_Ah);
    cudaGetSymbolAddress((void**)&Bh,     g_Bh);
    cudaGetSymbolAddress((void**)&u,      g_u);
    cudaGetSymbolAddress((void**)&scores, g_scores);
    cudaGetSymbolAddress((void**)&topk,   g_topk);
    cudaGetSymbolAddress((void**)&Q,      g_Q);
    cudaGetSymbolAddress((void**)&x3h,    g_x3h);
    cudaGetSymbolAddress((void**)&kk,     g_kk);
    cudaGetSymbolAddress((void**)&v,      g_v);
    cudaGetSymbolAddress((void**)&q,      g_q);
    cudaGetSymbolAddress((void**)&logits, g_logits);
    cudaGetSymbolAddress((void**)&stats,  g_stats);
    cudaGetSymbolAddress((void**)&O,      g_O);

    cudaFuncSetAttribute(tc_gemm, cudaFuncAttributeMaxDynamicSharedMemorySize, GEMM_SMEM);

    // 0. fold enc weights (fp32-exact gating path)
    fold_enc_k<<<IND / 8, 256>>>(W_feat, w_enc, u);
    fold_const_k<<<1, 512>>>(b_feat, w_enc, b_enc, u);
    // 1. convert inputs -> fp16; x = inputs @ W_feat + b_feat  (fp16 mma, fp32 accum)
    cvt_f16<<<(B_ * N_ * IND / 8 + 255) / 256, 256>>>(
        (const float4*)inputs, (uint4*)Ah, B_ * N_ * IND / 8);
    transpose_f16<<<dim3(IND / 32, HID / 32), 256>>>(W_feat, Bh, IND, HID);
    tc_gemm<<<dim3(HID / BNT, B_ * N_ / BMT), 256, GEMM_SMEM>>>(
        Ah, Bh, b_feat, b_feat, x, x, B_ * N_, IND);
    // 2. gate logits from raw inputs (fp32 exact)
    scores_k<<<(B_ * N_) / 8, 256>>>(inputs, u, scores);
    // 3. top-16 per batch
    topk_k<<<B_, 256>>>(scores, topk);
    // 4. Q = mean of selected (pre-relu) rows
    qmean_k<<<B_, HID>>>(x, topk, Q);
    // 5+6. fused relu + depthwise conv + residual -> x3 (fp16)
    conv_k<<<(B_ * NPAD * HID + 255) / 256, 256>>>(x, Q, conv_w, conv_b, x3h);
    // 7. cls token -> x3 row 0
    cls_k<<<B_, HID>>>(cls, x3h);
    // 8. fused K|V projection: Bh = [Wk^T | Wv^T], one GEMM with N=1024
    transpose_f16<<<dim3(HID / 32, HID / 32), 256>>>(Wk, Bh, HID, HID);
    transpose_f16<<<dim3(HID / 32, HID / 32), 256>>>(Wv, Bh + HID * HID, HID, HID);
    tc_gemm<<<dim3(2 * HID / BNT, (B_ * NTOK + BMT - 1) / BMT), 256, GEMM_SMEM>>>(
        x3h, Bh, bk, bv, kk, v, B_ * NTOK, HID);
    // 10. q = Q @ Wq + bq
    rowmat_k<<<B_, HID>>>(Q, Wq, bq, q);
    // 11. attention logits
    logits_k<<<dim3(B_ * HEADS, (NTOK + 255) / 256), 256>>>(q, kk, logits);
    // 12. softmax stats
    stats_k<<<B_ * HEADS, 256>>>(logits, stats);
    // 13. O = q + A @ v
    attno_k<<<B_ * HEADS, 256>>>(logits, stats, v, q, O);
    // 14. O += relu(O @ Wo + bo)
    otrans_k<<<B_, HID>>>(Wo, bo, O);
    // 15. out = O @ Wc + bc
    final_k<<<B_ * NCLS, 128>>>(O, Wc, bc, out);
}